// round 6
// baseline (speedup 1.0000x reference)
#include <cuda_runtime.h>
#include <math.h>

#define KNOTS_N 30
#define NSEG (KNOTS_N - 1)
#define EPSF 1e-12f
#define TPB 256
#define VEC 4
// f = u * FSCALE with u in [0,1]; FSCALE < 29 guarantees idx <= 28 with no clamp.
#define FSCALE 28.999998f

// ---------------------------------------------------------------------------
// Fused kernel (R4 launch shape): warp 0 of each block runs PCHIP prep (fp32,
// shuffle-parallel), then all warps stream x -> spline(x).
// Instruction-diet eval: FFMA.SAT + FMUL + F2I + I2F + FADD + 2xLDS.64 +
// 3xFFMA = 10 instructions/element.
// Coefficient tables as float2 pairs: (c0,c1) and (c2,c3); 29 entries over
// 16 bank-pair groups -> conflict degree <= 2.
// ---------------------------------------------------------------------------

struct Tables {
    float2 ab[NSEG];     // (c0, c1)
    float2 cd[NSEG];     // (c2, c3)
    float kn[KNOTS_N], ih[NSEG];
    float s1, s0;        // u = sat(fma(x, s1, s0)); s1 = 1/range, s0 = -k0/range
    int uni;
};

__device__ __forceinline__ void prep_warp0(const float* __restrict__ knots,
                                           const float* __restrict__ coeffs,
                                           Tables* s) {
    const int t = threadIdx.x;
    const unsigned FULL = 0xFFFFFFFFu;
    const bool kv = (t < KNOTS_N);
    const bool sv = (t < NSEG);

    float xt = kv ? knots[t]  : 0.0f;
    float yt = kv ? coeffs[t] : 0.0f;

    float xn = __shfl_down_sync(FULL, xt, 1);
    float yn = __shfl_down_sync(FULL, yt, 1);
    float h = xn - xt;
    float delta = (yn - yt) / (h + EPSF);

    float h_m1 = __shfl_up_sync(FULL, h, 1);
    float d_m1 = __shfl_up_sync(FULL, delta, 1);

    float d = 0.0f;
    if (t >= 1 && t < KNOTS_N - 1) {
        float w1 = 2.0f * h + h_m1;
        float w2 = h + 2.0f * h_m1;
        bool same = (d_m1 * delta) > 0.0f;
        float dint = (w1 + w2) / (w1 / (d_m1 + EPSF) + w2 / (delta + EPSF));
        d = same ? dint : 0.0f;
    }
    {
        float h0  = __shfl_sync(FULL, h, 0),      h1  = __shfl_sync(FULL, h, 1);
        float de0 = __shfl_sync(FULL, delta, 0),  de1 = __shfl_sync(FULL, delta, 1);
        if (t == 0) {
            float d0 = ((2.0f * h0 + h1) * de0 - h0 * de1) / (h0 + h1 + EPSF);
            if (d0 * de0 <= 0.0f) d0 = 0.0f;
            else if (fabsf(d0) > 3.0f * fabsf(de0)) d0 = 3.0f * de0;
            d = d0;
        }
    }
    {
        float hN1 = __shfl_sync(FULL, h, NSEG-1), hN2 = __shfl_sync(FULL, h, NSEG-2);
        float dN1 = __shfl_sync(FULL, delta, NSEG-1), dN2 = __shfl_sync(FULL, delta, NSEG-2);
        if (t == KNOTS_N - 1) {
            float dN = ((2.0f * hN1 + hN2) * dN1 - hN1 * dN2) / (hN1 + hN2 + EPSF);
            if (dN * dN1 <= 0.0f) dN = 0.0f;
            else if (fabsf(dN) > 3.0f * fabsf(dN1)) dN = 3.0f * dN1;
            d = dN;
        }
    }

    float d_p1 = __shfl_down_sync(FULL, d, 1);
    if (sv) {
        if (fabsf(h) < EPSF) {
            s->ab[t] = make_float2(yt, 0.0f);
            s->cd[t] = make_float2(0.0f, 0.0f);
            s->ih[t] = 0.0f;
        } else {
            float hdk = h * d, hdk1 = h * d_p1;
            float c2 = fmaf(-2.0f, hdk, fmaf(3.0f, yn - yt, -hdk1));
            float c3 = fmaf(2.0f, yt - yn, hdk + hdk1);
            s->ab[t] = make_float2(yt, hdk);
            s->cd[t] = make_float2(c2, c3);
            s->ih[t] = 1.0f / h;
        }
    }
    if (kv) s->kn[t] = xt;

    float k0   = __shfl_sync(FULL, xt, 0);
    float kend = __shfl_sync(FULL, xt, KNOTS_N - 1);
    float range = kend - k0;
    float dxu = range / (float)NSEG;
    float tol = 1e-5f * fmaxf(fabsf(range), 1.0f);
    bool okk = !kv || (fabsf(xt - fmaf((float)t, dxu, k0)) <= tol);
    bool uni = __all_sync(FULL, okk) && (dxu > 0.0f);
    if (t == 0) {
        float inv_range = (range > 0.0f) ? (1.0f / range) : 0.0f;
        s->s1 = inv_range;
        s->s0 = -k0 * inv_range;
        s->uni = uni ? 1 : 0;
    }
}

__device__ __forceinline__ float eval_uni(float xv, const Tables* s,
                                          float s1, float s0) {
    float u = __saturatef(fmaf(xv, s1, s0));   // FFMA.SAT
    float f = u * FSCALE;                      // FMUL; f in [0, 29)
    int idx = (int)f;                          // F2I.RZ; 0..28 guaranteed
    float tt = f - (float)idx;                 // I2F + FADD
    float2 p = s->ab[idx];                     // LDS.64
    float2 q = s->cd[idx];                     // LDS.64
    return fmaf(fmaf(fmaf(q.y, tt, q.x), tt, p.y), tt, p.x);
}

__device__ __forceinline__ float eval_nu(float xv, const Tables* s,
                                         float klo, float khi) {
    float xc = fminf(fmaxf(xv, klo), khi);
    int lo = 0, hi = KNOTS_N;
    while (lo < hi) {
        int mid = (lo + hi) >> 1;
        if (s->kn[mid] < xc) lo = mid + 1;
        else hi = mid;
    }
    int idx = max(min(lo - 1, NSEG - 1), 0);
    float tt = (xc - s->kn[idx]) * s->ih[idx];
    float2 p = s->ab[idx];
    float2 q = s->cd[idx];
    return fmaf(fmaf(fmaf(q.y, tt, q.x), tt, p.y), tt, p.x);
}

__device__ __forceinline__ float4 eval_vec4_uni(float4 v, const Tables* s,
                                                float s1, float s0) {
    float4 r;
    r.x = eval_uni(v.x, s, s1, s0);
    r.y = eval_uni(v.y, s, s1, s0);
    r.z = eval_uni(v.z, s, s1, s0);
    r.w = eval_uni(v.w, s, s1, s0);
    return r;
}

__device__ __forceinline__ float4 eval_vec4_nu(float4 v, const Tables* s,
                                               float klo, float khi) {
    float4 r;
    r.x = eval_nu(v.x, s, klo, khi);
    r.y = eval_nu(v.y, s, klo, khi);
    r.z = eval_nu(v.z, s, klo, khi);
    r.w = eval_nu(v.w, s, klo, khi);
    return r;
}

template <bool EXACT>
__global__ void __launch_bounds__(TPB, 8)
spline_fused_kernel(const float* __restrict__ x,
                    const float* __restrict__ knots,
                    const float* __restrict__ coeffs,
                    float* __restrict__ out, int n) {
    __shared__ Tables s;
    const int t = threadIdx.x;

    if (t < 32) prep_warp0(knots, coeffs, &s);
    __syncthreads();

    const float s1 = s.s1;
    const float s0 = s.s0;
    const int uni = s.uni;

    const int nvec = n >> 2;
    const int base = blockIdx.x * (TPB * VEC) + t;
    const float4* __restrict__ xv = reinterpret_cast<const float4*>(x);
    float4* __restrict__ ov = reinterpret_cast<float4*>(out);

    if (uni) {
        if (EXACT) {
            // 4 front-batched independent LDG.128, zero predicates.
            float4 v0 = __ldcs(xv + base);
            float4 v1 = __ldcs(xv + base + TPB);
            float4 v2 = __ldcs(xv + base + 2 * TPB);
            float4 v3 = __ldcs(xv + base + 3 * TPB);
            __stcs(ov + base,           eval_vec4_uni(v0, &s, s1, s0));
            __stcs(ov + base + TPB,     eval_vec4_uni(v1, &s, s1, s0));
            __stcs(ov + base + 2 * TPB, eval_vec4_uni(v2, &s, s1, s0));
            __stcs(ov + base + 3 * TPB, eval_vec4_uni(v3, &s, s1, s0));
        } else {
#pragma unroll
            for (int i = 0; i < VEC; i++) {
                const int gid = base + i * TPB;
                if (gid < nvec) {
                    float4 v = __ldcs(xv + gid);
                    __stcs(ov + gid, eval_vec4_uni(v, &s, s1, s0));
                }
            }
        }
    } else {
        const float klo = s.kn[0];
        const float khi = s.kn[KNOTS_N - 1];
#pragma unroll
        for (int i = 0; i < VEC; i++) {
            const int gid = base + i * TPB;
            if (EXACT || gid < nvec) {
                float4 v = __ldcs(xv + gid);
                __stcs(ov + gid, eval_vec4_nu(v, &s, klo, khi));
            }
        }
    }

    if (!EXACT) {
        const int rem = n & 3;
        if (blockIdx.x == 0 && t < rem) {
            const int i = (nvec << 2) + t;
            float xvv = x[i];
            out[i] = uni ? eval_uni(xvv, &s, s1, s0)
                         : eval_nu(xvv, &s, s.kn[0], s.kn[KNOTS_N - 1]);
        }
    }
}

extern "C" void kernel_launch(void* const* d_in, const int* in_sizes, int n_in,
                              void* d_out, int out_size) {
    const float* x      = (const float*)d_in[0];
    const float* knots  = (const float*)d_in[1];
    const float* coeffs = (const float*)d_in[2];
    float* out = (float*)d_out;
    const int n = in_sizes[0];

    const int nvec = n >> 2;
    const int per_block = TPB * VEC;

    if (n >= 4 && (n & 3) == 0 && (nvec % per_block) == 0) {
        const int grid = nvec / per_block;
        spline_fused_kernel<true><<<grid, TPB>>>(x, knots, coeffs, out, n);
    } else {
        int grid = (nvec + per_block - 1) / per_block;
        if (grid < 1) grid = 1;
        spline_fused_kernel<false><<<grid, TPB>>>(x, knots, coeffs, out, n);
    }
}

// round 8
// speedup vs baseline: 1.1214x; 1.1214x over previous
#include <cuda_runtime.h>
#include <math.h>

#define KNOTS_N 30
#define NSEG (KNOTS_N - 1)
#define EPSF 1e-12f
#define TPB 256
#define VEC 4
// f = u * FSCALE with u in [0,1]; FSCALE < 29 guarantees idx <= 28 with no clamp.
#define FSCALE 28.999998f

// ---------------------------------------------------------------------------
// Fused kernel (R4 launch shape / memory layout + R6 index math):
//  - warp 0 of each block: PCHIP prep (fp32, shuffle-parallel)
//  - SoA scalar tables: 29 entries -> 29 distinct banks -> every LDS.32 is a
//    single conflict-free wavefront (4 wavefronts/element = LDS.128 floor,
//    no conflict risk). float2/float4 packing measurably worse (R1, R6).
//  - index: FFMA.SAT + FMUL + F2I + I2F + FADD (no clamps).
//  - loads default policy (x partially L2-resident across graph replays),
//    stores streaming (.cs) so output doesn't evict x from L2.
// ---------------------------------------------------------------------------

struct Tables {
    float c0[NSEG], c1[NSEG], c2[NSEG], c3[NSEG];
    float kn[KNOTS_N], ih[NSEG];
    float s1, s0;        // u = sat(fma(x, s1, s0)); s1 = 1/range, s0 = -k0/range
    int uni;
};

__device__ __forceinline__ void prep_warp0(const float* __restrict__ knots,
                                           const float* __restrict__ coeffs,
                                           Tables* s) {
    const int t = threadIdx.x;
    const unsigned FULL = 0xFFFFFFFFu;
    const bool kv = (t < KNOTS_N);
    const bool sv = (t < NSEG);

    float xt = kv ? knots[t]  : 0.0f;
    float yt = kv ? coeffs[t] : 0.0f;

    float xn = __shfl_down_sync(FULL, xt, 1);
    float yn = __shfl_down_sync(FULL, yt, 1);
    float h = xn - xt;
    float delta = (yn - yt) / (h + EPSF);

    float h_m1 = __shfl_up_sync(FULL, h, 1);
    float d_m1 = __shfl_up_sync(FULL, delta, 1);

    float d = 0.0f;
    if (t >= 1 && t < KNOTS_N - 1) {
        float w1 = 2.0f * h + h_m1;
        float w2 = h + 2.0f * h_m1;
        bool same = (d_m1 * delta) > 0.0f;
        float dint = (w1 + w2) / (w1 / (d_m1 + EPSF) + w2 / (delta + EPSF));
        d = same ? dint : 0.0f;
    }
    {
        float h0  = __shfl_sync(FULL, h, 0),      h1  = __shfl_sync(FULL, h, 1);
        float de0 = __shfl_sync(FULL, delta, 0),  de1 = __shfl_sync(FULL, delta, 1);
        if (t == 0) {
            float d0 = ((2.0f * h0 + h1) * de0 - h0 * de1) / (h0 + h1 + EPSF);
            if (d0 * de0 <= 0.0f) d0 = 0.0f;
            else if (fabsf(d0) > 3.0f * fabsf(de0)) d0 = 3.0f * de0;
            d = d0;
        }
    }
    {
        float hN1 = __shfl_sync(FULL, h, NSEG-1), hN2 = __shfl_sync(FULL, h, NSEG-2);
        float dN1 = __shfl_sync(FULL, delta, NSEG-1), dN2 = __shfl_sync(FULL, delta, NSEG-2);
        if (t == KNOTS_N - 1) {
            float dN = ((2.0f * hN1 + hN2) * dN1 - hN1 * dN2) / (hN1 + hN2 + EPSF);
            if (dN * dN1 <= 0.0f) dN = 0.0f;
            else if (fabsf(dN) > 3.0f * fabsf(dN1)) dN = 3.0f * dN1;
            d = dN;
        }
    }

    float d_p1 = __shfl_down_sync(FULL, d, 1);
    if (sv) {
        if (fabsf(h) < EPSF) {
            s->c0[t] = yt; s->c1[t] = 0.0f; s->c2[t] = 0.0f; s->c3[t] = 0.0f;
            s->ih[t] = 0.0f;
        } else {
            float hdk = h * d, hdk1 = h * d_p1;
            s->c0[t] = yt;
            s->c1[t] = hdk;
            s->c2[t] = fmaf(-2.0f, hdk, fmaf(3.0f, yn - yt, -hdk1));
            s->c3[t] = fmaf(2.0f, yt - yn, hdk + hdk1);
            s->ih[t] = 1.0f / h;
        }
    }
    if (kv) s->kn[t] = xt;

    float k0   = __shfl_sync(FULL, xt, 0);
    float kend = __shfl_sync(FULL, xt, KNOTS_N - 1);
    float range = kend - k0;
    float dxu = range / (float)NSEG;
    float tol = 1e-5f * fmaxf(fabsf(range), 1.0f);
    bool okk = !kv || (fabsf(xt - fmaf((float)t, dxu, k0)) <= tol);
    bool uni = __all_sync(FULL, okk) && (dxu > 0.0f);
    if (t == 0) {
        float inv_range = (range > 0.0f) ? (1.0f / range) : 0.0f;
        s->s1 = inv_range;
        s->s0 = -k0 * inv_range;
        s->uni = uni ? 1 : 0;
    }
}

__device__ __forceinline__ float eval_uni(float xv, const Tables* s,
                                          float s1, float s0) {
    float u = __saturatef(fmaf(xv, s1, s0));   // FFMA.SAT
    float f = u * FSCALE;                      // FMUL; f in [0, 29)
    int idx = (int)f;                          // F2I.RZ; 0..28 guaranteed
    float tt = f - (float)idx;                 // I2F + FADD
    float c3 = s->c3[idx], c2 = s->c2[idx];    // LDS.32 x4, conflict-free
    float c1 = s->c1[idx], c0 = s->c0[idx];
    return fmaf(fmaf(fmaf(c3, tt, c2), tt, c1), tt, c0);
}

__device__ __forceinline__ float eval_nu(float xv, const Tables* s,
                                         float klo, float khi) {
    float xc = fminf(fmaxf(xv, klo), khi);
    int lo = 0, hi = KNOTS_N;
    while (lo < hi) {
        int mid = (lo + hi) >> 1;
        if (s->kn[mid] < xc) lo = mid + 1;
        else hi = mid;
    }
    int idx = max(min(lo - 1, NSEG - 1), 0);
    float tt = (xc - s->kn[idx]) * s->ih[idx];
    return fmaf(fmaf(fmaf(s->c3[idx], tt, s->c2[idx]), tt, s->c1[idx]), tt, s->c0[idx]);
}

__device__ __forceinline__ float4 eval_vec4_uni(float4 v, const Tables* s,
                                                float s1, float s0) {
    float4 r;
    r.x = eval_uni(v.x, s, s1, s0);
    r.y = eval_uni(v.y, s, s1, s0);
    r.z = eval_uni(v.z, s, s1, s0);
    r.w = eval_uni(v.w, s, s1, s0);
    return r;
}

__device__ __forceinline__ float4 eval_vec4_nu(float4 v, const Tables* s,
                                               float klo, float khi) {
    float4 r;
    r.x = eval_nu(v.x, s, klo, khi);
    r.y = eval_nu(v.y, s, klo, khi);
    r.z = eval_nu(v.z, s, klo, khi);
    r.w = eval_nu(v.w, s, klo, khi);
    return r;
}

template <bool EXACT>
__global__ void __launch_bounds__(TPB, 8)
spline_fused_kernel(const float* __restrict__ x,
                    const float* __restrict__ knots,
                    const float* __restrict__ coeffs,
                    float* __restrict__ out, int n) {
    __shared__ Tables s;
    const int t = threadIdx.x;

    if (t < 32) prep_warp0(knots, coeffs, &s);
    __syncthreads();

    const float s1 = s.s1;
    const float s0 = s.s0;
    const int uni = s.uni;

    const int nvec = n >> 2;
    const int base = blockIdx.x * (TPB * VEC) + t;
    const float4* __restrict__ xv = reinterpret_cast<const float4*>(x);
    float4* __restrict__ ov = reinterpret_cast<float4*>(out);

    if (uni) {
        // 2+2 staged pipeline (R4-proven): default-policy loads, streaming stores.
        float4 a, b;
        if (EXACT || base < nvec)       a = xv[base];
        if (EXACT || base + TPB < nvec) b = xv[base + TPB];
#pragma unroll
        for (int i = 0; i < VEC; i++) {
            const int gid = base + i * TPB;
            if (EXACT || gid < nvec) {
                float4 v = (i & 1) ? b : a;
                const int pf = gid + 2 * TPB;
                if (i + 2 < VEC && (EXACT || pf < nvec)) {
                    if (i & 1) b = xv[pf];
                    else       a = xv[pf];
                }
                __stcs(ov + gid, eval_vec4_uni(v, &s, s1, s0));
            }
        }
    } else {
        const float klo = s.kn[0];
        const float khi = s.kn[KNOTS_N - 1];
#pragma unroll
        for (int i = 0; i < VEC; i++) {
            const int gid = base + i * TPB;
            if (EXACT || gid < nvec) {
                float4 v = xv[gid];
                __stcs(ov + gid, eval_vec4_nu(v, &s, klo, khi));
            }
        }
    }

    if (!EXACT) {
        const int rem = n & 3;
        if (blockIdx.x == 0 && t < rem) {
            const int i = (nvec << 2) + t;
            float xvv = x[i];
            out[i] = uni ? eval_uni(xvv, &s, s1, s0)
                         : eval_nu(xvv, &s, s.kn[0], s.kn[KNOTS_N - 1]);
        }
    }
}

extern "C" void kernel_launch(void* const* d_in, const int* in_sizes, int n_in,
                              void* d_out, int out_size) {
    const float* x      = (const float*)d_in[0];
    const float* knots  = (const float*)d_in[1];
    const float* coeffs = (const float*)d_in[2];
    float* out = (float*)d_out;
    const int n = in_sizes[0];

    const int nvec = n >> 2;
    const int per_block = TPB * VEC;

    if (n >= 4 && (n & 3) == 0 && (nvec % per_block) == 0) {
        const int grid = nvec / per_block;
        spline_fused_kernel<true><<<grid, TPB>>>(x, knots, coeffs, out, n);
    } else {
        int grid = (nvec + per_block - 1) / per_block;
        if (grid < 1) grid = 1;
        spline_fused_kernel<false><<<grid, TPB>>>(x, knots, coeffs, out, n);
    }
}

// round 11
// speedup vs baseline: 1.1388x; 1.0155x over previous
#include <cuda_runtime.h>
#include <math.h>

#define KNOTS_N 30
#define NSEG (KNOTS_N - 1)
#define EPSF 1e-12f
#define TPB 256
#define VEC 4
// f = u * FSCALE with u in [0,1]; FSCALE < 29 guarantees idx <= 28 with no clamp.
#define FSCALE 28.999998f

// ---------------------------------------------------------------------------
// Fused kernel, all empirically-proven pieces:
//  - warp 0 per block: PCHIP prep (fp32 shuffle-parallel)     [R3]
//  - SoA scalar tables: 29 entries -> 29 banks, every LDS.32 is one
//    conflict-free wavefront (float2/float4 packing worse: R1, R6)
//  - saturate-scale index: FFMA.SAT+FMUL+F2I+I2F+FADD, no clamps  [R6]
//  - __ldcs loads / __stcs stores (touch-once streams)        [R4 vs R8]
//  - EXACT template: zero predicates, 4 front-batched LDG.128 [R4/R5]
//  - __launch_bounds__(256,8): 32 regs, 64 warps/SM           [R4]
// ---------------------------------------------------------------------------

struct Tables {
    float c0[NSEG], c1[NSEG], c2[NSEG], c3[NSEG];
    float kn[KNOTS_N], ih[NSEG];
    float s1, s0;        // u = sat(fma(x, s1, s0)); s1 = 1/range, s0 = -k0/range
    int uni;
};

__device__ __forceinline__ void prep_warp0(const float* __restrict__ knots,
                                           const float* __restrict__ coeffs,
                                           Tables* s) {
    const int t = threadIdx.x;
    const unsigned FULL = 0xFFFFFFFFu;
    const bool kv = (t < KNOTS_N);
    const bool sv = (t < NSEG);

    float xt = kv ? knots[t]  : 0.0f;
    float yt = kv ? coeffs[t] : 0.0f;

    float xn = __shfl_down_sync(FULL, xt, 1);
    float yn = __shfl_down_sync(FULL, yt, 1);
    float h = xn - xt;
    float delta = (yn - yt) / (h + EPSF);

    float h_m1 = __shfl_up_sync(FULL, h, 1);
    float d_m1 = __shfl_up_sync(FULL, delta, 1);

    float d = 0.0f;
    if (t >= 1 && t < KNOTS_N - 1) {
        float w1 = 2.0f * h + h_m1;
        float w2 = h + 2.0f * h_m1;
        bool same = (d_m1 * delta) > 0.0f;
        float dint = (w1 + w2) / (w1 / (d_m1 + EPSF) + w2 / (delta + EPSF));
        d = same ? dint : 0.0f;
    }
    {
        float h0  = __shfl_sync(FULL, h, 0),      h1  = __shfl_sync(FULL, h, 1);
        float de0 = __shfl_sync(FULL, delta, 0),  de1 = __shfl_sync(FULL, delta, 1);
        if (t == 0) {
            float d0 = ((2.0f * h0 + h1) * de0 - h0 * de1) / (h0 + h1 + EPSF);
            if (d0 * de0 <= 0.0f) d0 = 0.0f;
            else if (fabsf(d0) > 3.0f * fabsf(de0)) d0 = 3.0f * de0;
            d = d0;
        }
    }
    {
        float hN1 = __shfl_sync(FULL, h, NSEG-1), hN2 = __shfl_sync(FULL, h, NSEG-2);
        float dN1 = __shfl_sync(FULL, delta, NSEG-1), dN2 = __shfl_sync(FULL, delta, NSEG-2);
        if (t == KNOTS_N - 1) {
            float dN = ((2.0f * hN1 + hN2) * dN1 - hN1 * dN2) / (hN1 + hN2 + EPSF);
            if (dN * dN1 <= 0.0f) dN = 0.0f;
            else if (fabsf(dN) > 3.0f * fabsf(dN1)) dN = 3.0f * dN1;
            d = dN;
        }
    }

    float d_p1 = __shfl_down_sync(FULL, d, 1);
    if (sv) {
        if (fabsf(h) < EPSF) {
            s->c0[t] = yt; s->c1[t] = 0.0f; s->c2[t] = 0.0f; s->c3[t] = 0.0f;
            s->ih[t] = 0.0f;
        } else {
            float hdk = h * d, hdk1 = h * d_p1;
            s->c0[t] = yt;
            s->c1[t] = hdk;
            s->c2[t] = fmaf(-2.0f, hdk, fmaf(3.0f, yn - yt, -hdk1));
            s->c3[t] = fmaf(2.0f, yt - yn, hdk + hdk1);
            s->ih[t] = 1.0f / h;
        }
    }
    if (kv) s->kn[t] = xt;

    float k0   = __shfl_sync(FULL, xt, 0);
    float kend = __shfl_sync(FULL, xt, KNOTS_N - 1);
    float range = kend - k0;
    float dxu = range / (float)NSEG;
    float tol = 1e-5f * fmaxf(fabsf(range), 1.0f);
    bool okk = !kv || (fabsf(xt - fmaf((float)t, dxu, k0)) <= tol);
    bool uni = __all_sync(FULL, okk) && (dxu > 0.0f);
    if (t == 0) {
        float inv_range = (range > 0.0f) ? (1.0f / range) : 0.0f;
        s->s1 = inv_range;
        s->s0 = -k0 * inv_range;
        s->uni = uni ? 1 : 0;
    }
}

__device__ __forceinline__ float eval_uni(float xv, const Tables* s,
                                          float s1, float s0) {
    float u = __saturatef(fmaf(xv, s1, s0));   // FFMA.SAT
    float f = u * FSCALE;                      // FMUL; f in [0, 29)
    int idx = (int)f;                          // F2I.RZ; 0..28 guaranteed
    float tt = f - (float)idx;                 // I2F + FADD
    float c3 = s->c3[idx], c2 = s->c2[idx];    // 4x LDS.32, conflict-free
    float c1 = s->c1[idx], c0 = s->c0[idx];
    return fmaf(fmaf(fmaf(c3, tt, c2), tt, c1), tt, c0);
}

__device__ __forceinline__ float eval_nu(float xv, const Tables* s,
                                         float klo, float khi) {
    float xc = fminf(fmaxf(xv, klo), khi);
    int lo = 0, hi = KNOTS_N;
    while (lo < hi) {
        int mid = (lo + hi) >> 1;
        if (s->kn[mid] < xc) lo = mid + 1;
        else hi = mid;
    }
    int idx = max(min(lo - 1, NSEG - 1), 0);
    float tt = (xc - s->kn[idx]) * s->ih[idx];
    return fmaf(fmaf(fmaf(s->c3[idx], tt, s->c2[idx]), tt, s->c1[idx]), tt, s->c0[idx]);
}

__device__ __forceinline__ float4 eval_vec4_uni(float4 v, const Tables* s,
                                                float s1, float s0) {
    float4 r;
    r.x = eval_uni(v.x, s, s1, s0);
    r.y = eval_uni(v.y, s, s1, s0);
    r.z = eval_uni(v.z, s, s1, s0);
    r.w = eval_uni(v.w, s, s1, s0);
    return r;
}

__device__ __forceinline__ float4 eval_vec4_nu(float4 v, const Tables* s,
                                               float klo, float khi) {
    float4 r;
    r.x = eval_nu(v.x, s, klo, khi);
    r.y = eval_nu(v.y, s, klo, khi);
    r.z = eval_nu(v.z, s, klo, khi);
    r.w = eval_nu(v.w, s, klo, khi);
    return r;
}

template <bool EXACT>
__global__ void __launch_bounds__(TPB, 8)
spline_fused_kernel(const float* __restrict__ x,
                    const float* __restrict__ knots,
                    const float* __restrict__ coeffs,
                    float* __restrict__ out, int n) {
    __shared__ Tables s;
    const int t = threadIdx.x;

    if (t < 32) prep_warp0(knots, coeffs, &s);
    __syncthreads();

    const float s1 = s.s1;
    const float s0 = s.s0;
    const int uni = s.uni;

    const int nvec = n >> 2;
    const int base = blockIdx.x * (TPB * VEC) + t;
    const float4* __restrict__ xv = reinterpret_cast<const float4*>(x);
    float4* __restrict__ ov = reinterpret_cast<float4*>(out);

    if (uni) {
        if (EXACT) {
            // 4 fully front-batched independent LDG.128 (MLP_p1 = 4).
            float4 v0 = __ldcs(xv + base);
            float4 v1 = __ldcs(xv + base + TPB);
            float4 v2 = __ldcs(xv + base + 2 * TPB);
            float4 v3 = __ldcs(xv + base + 3 * TPB);
            __stcs(ov + base,           eval_vec4_uni(v0, &s, s1, s0));
            __stcs(ov + base + TPB,     eval_vec4_uni(v1, &s, s1, s0));
            __stcs(ov + base + 2 * TPB, eval_vec4_uni(v2, &s, s1, s0));
            __stcs(ov + base + 3 * TPB, eval_vec4_uni(v3, &s, s1, s0));
        } else {
#pragma unroll
            for (int i = 0; i < VEC; i++) {
                const int gid = base + i * TPB;
                if (gid < nvec) {
                    float4 v = __ldcs(xv + gid);
                    __stcs(ov + gid, eval_vec4_uni(v, &s, s1, s0));
                }
            }
        }
    } else {
        const float klo = s.kn[0];
        const float khi = s.kn[KNOTS_N - 1];
#pragma unroll
        for (int i = 0; i < VEC; i++) {
            const int gid = base + i * TPB;
            if (EXACT || gid < nvec) {
                float4 v = __ldcs(xv + gid);
                __stcs(ov + gid, eval_vec4_nu(v, &s, klo, khi));
            }
        }
    }

    if (!EXACT) {
        const int rem = n & 3;
        if (blockIdx.x == 0 && t < rem) {
            const int i = (nvec << 2) + t;
            float xvv = x[i];
            out[i] = uni ? eval_uni(xvv, &s, s1, s0)
                         : eval_nu(xvv, &s, s.kn[0], s.kn[KNOTS_N - 1]);
        }
    }
}

extern "C" void kernel_launch(void* const* d_in, const int* in_sizes, int n_in,
                              void* d_out, int out_size) {
    const float* x      = (const float*)d_in[0];
    const float* knots  = (const float*)d_in[1];
    const float* coeffs = (const float*)d_in[2];
    float* out = (float*)d_out;
    const int n = in_sizes[0];

    const int nvec = n >> 2;
    const int per_block = TPB * VEC;

    if (n >= 4 && (n & 3) == 0 && (nvec % per_block) == 0) {
        const int grid = nvec / per_block;
        spline_fused_kernel<true><<<grid, TPB>>>(x, knots, coeffs, out, n);
    } else {
        int grid = (nvec + per_block - 1) / per_block;
        if (grid < 1) grid = 1;
        spline_fused_kernel<false><<<grid, TPB>>>(x, knots, coeffs, out, n);
    }
}